// round 8
// baseline (speedup 1.0000x reference)
#include <cuda_runtime.h>
#include <cuda_fp16.h>

#define NUM_USERS 100000
#define NUM_ITEMS 50000
#define N_NODES   150000
#define DIM       64
#define NUM_EDGES 4000000

// Scratch (allocation-free rule: __device__ globals).
__device__ __half2 g_bufA[N_NODES * DIM / 2];
__device__ __half2 g_bufB[N_NODES * DIM / 2];
__device__ int2    g_edges[NUM_EDGES];      // interleaved {col, val-bits}
__device__ int     g_hist[N_NODES];
__device__ int     g_rowptr[N_NODES + 1];
__device__ int     g_cursor[N_NODES];

__device__ __forceinline__ void cp_async4(unsigned int smem_dst, const void* gsrc)
{
    asm volatile("cp.async.ca.shared.global [%0], [%1], 4;"
                 :: "r"(smem_dst), "l"(gsrc) : "memory");
}

// -------------------------------------------------------------------------
// Kernel 1: fused init — convert concat(user,item) embeddings -> fp16 bufA,
// zero histogram, AND accumulate the degree histogram (8 edges/thread).
// -------------------------------------------------------------------------
__global__ void lgcn_convert(const float* __restrict__ user_emb,
                             const float* __restrict__ item_emb)
{
    int i = blockIdx.x * blockDim.x + threadIdx.x;
    const int total8 = N_NODES * DIM / 8;
    if (i < total8) {
        const int user8 = NUM_USERS * DIM / 8;
        const float4* s = (i < user8)
            ? (const float4*)user_emb + 2 * (size_t)i
            : (const float4*)item_emb + 2 * (size_t)(i - user8);
        float4 a = s[0];
        float4 b = s[1];
        __half2 h0 = __floats2half2_rn(a.x, a.y);
        __half2 h1 = __floats2half2_rn(a.z, a.w);
        __half2 h2 = __floats2half2_rn(b.x, b.y);
        __half2 h3 = __floats2half2_rn(b.z, b.w);
        uint4 p;
        p.x = *(unsigned int*)&h0;
        p.y = *(unsigned int*)&h1;
        p.z = *(unsigned int*)&h2;
        p.w = *(unsigned int*)&h3;
        ((uint4*)g_bufA)[i] = p;
    }
    if (i < N_NODES) g_hist[i] = 0;
}

// -------------------------------------------------------------------------
// Kernel 2: degree histogram, 8 edges/thread (2x int4 loads).
// -------------------------------------------------------------------------
__global__ void lgcn_hist(const int* __restrict__ edge_row)
{
    int i = blockIdx.x * blockDim.x + threadIdx.x;
    if (i >= NUM_EDGES / 8) return;
    int4 r0 = ((const int4*)edge_row)[i * 2];
    int4 r1 = ((const int4*)edge_row)[i * 2 + 1];
    atomicAdd(&g_hist[r0.x], 1);
    atomicAdd(&g_hist[r0.y], 1);
    atomicAdd(&g_hist[r0.z], 1);
    atomicAdd(&g_hist[r0.w], 1);
    atomicAdd(&g_hist[r1.x], 1);
    atomicAdd(&g_hist[r1.y], 1);
    atomicAdd(&g_hist[r1.z], 1);
    atomicAdd(&g_hist[r1.w], 1);
}

// -------------------------------------------------------------------------
// Kernel 3: single-block exclusive scan -> row_ptr + cursor.
// -------------------------------------------------------------------------
__global__ void lgcn_scan()
{
    const int T = 1024;
    const int CHUNK = (N_NODES + T - 1) / T;   // 147
    __shared__ int s_part[T];

    int t   = threadIdx.x;
    int beg = t * CHUNK;
    int end = min(beg + CHUNK, N_NODES);

    int sum = 0;
    for (int i = beg; i < end; i++) sum += g_hist[i];
    s_part[t] = sum;
    __syncthreads();

    for (int off = 1; off < T; off <<= 1) {
        int v = (t >= off) ? s_part[t - off] : 0;
        __syncthreads();
        s_part[t] += v;
        __syncthreads();
    }

    int run = s_part[t] - sum;
    for (int i = beg; i < end; i++) {
        g_rowptr[i] = run;
        g_cursor[i] = run;
        run += g_hist[i];
    }
    if (t == 0) g_rowptr[N_NODES] = NUM_EDGES;
}

// -------------------------------------------------------------------------
// Kernel 4: scatter edges into row-sorted interleaved array, 8 edges/thread.
// -------------------------------------------------------------------------
__global__ void lgcn_scatter(const float* __restrict__ edge_vals,
                             const int*   __restrict__ edge_row,
                             const int*   __restrict__ edge_col)
{
    int i = blockIdx.x * blockDim.x + threadIdx.x;
    if (i >= NUM_EDGES / 8) return;
    int4   r0 = ((const int4*)edge_row)[i * 2];
    int4   r1 = ((const int4*)edge_row)[i * 2 + 1];
    int4   c0 = ((const int4*)edge_col)[i * 2];
    int4   c1 = ((const int4*)edge_col)[i * 2 + 1];
    float4 v0 = ((const float4*)edge_vals)[i * 2];
    float4 v1 = ((const float4*)edge_vals)[i * 2 + 1];

    int p0 = atomicAdd(&g_cursor[r0.x], 1);
    int p1 = atomicAdd(&g_cursor[r0.y], 1);
    int p2 = atomicAdd(&g_cursor[r0.z], 1);
    int p3 = atomicAdd(&g_cursor[r0.w], 1);
    int p4 = atomicAdd(&g_cursor[r1.x], 1);
    int p5 = atomicAdd(&g_cursor[r1.y], 1);
    int p6 = atomicAdd(&g_cursor[r1.z], 1);
    int p7 = atomicAdd(&g_cursor[r1.w], 1);

    g_edges[p0] = make_int2(c0.x, __float_as_int(v0.x));
    g_edges[p1] = make_int2(c0.y, __float_as_int(v0.y));
    g_edges[p2] = make_int2(c0.z, __float_as_int(v0.z));
    g_edges[p3] = make_int2(c0.w, __float_as_int(v0.w));
    g_edges[p4] = make_int2(c1.x, __float_as_int(v1.x));
    g_edges[p5] = make_int2(c1.y, __float_as_int(v1.y));
    g_edges[p6] = make_int2(c1.z, __float_as_int(v1.z));
    g_edges[p7] = make_int2(c1.w, __float_as_int(v1.w));
}

// -------------------------------------------------------------------------
// Kernel 5: warp-per-node CSR gather with cp.async row staging.
// Per 32-edge chunk: issue up to 32 LDGSTS (one fp16 row each, MLP=32,
// zero register cost), one commit + wait, then conflict-free LDS consume
// with fp32 accumulation.
// MODE 0: out = emb_f32 + acc; nxt = half(acc).
// MODE 1: out += acc;          nxt = half(acc).
// MODE 2: out = (out + acc) * 0.25.
// -------------------------------------------------------------------------
template<int MODE>
__global__ void __launch_bounds__(256)
lgcn_gather(const __half2* __restrict__ cur,
            const float*   __restrict__ user_emb,
            const float*   __restrict__ item_emb,
            __half2*       __restrict__ nxt,
            float*         __restrict__ out)
{
    __shared__ int2 s_edges[8][32];
    __shared__ __align__(16) unsigned int s_rows[8][32][32];  // 32 KB

    const int wslot = threadIdx.x >> 5;
    const int lane  = threadIdx.x & 31;
    const int node  = blockIdx.x * 8 + wslot;
    if (node >= N_NODES) return;

    const int start = g_rowptr[node];
    const int end   = g_rowptr[node + 1];

    float2 acc = make_float2(0.f, 0.f);

    const unsigned int rowbase =
        (unsigned int)__cvta_generic_to_shared(&s_rows[wslot][0][lane]);
    const char* curb = (const char*)cur;

    for (int base = start; base < end; base += 32) {
        int idx = base + lane;
        if (idx < end) s_edges[wslot][lane] = g_edges[idx];
        __syncwarp();
        const int m = min(32, end - base);

        // Issue phase: one 128 B row per edge, all in flight at once.
        #pragma unroll 4
        for (int j = 0; j < m; j++) {
            int col = s_edges[wslot][j].x;
            const void* src = curb + ((size_t)col << 7) + (lane << 2);
            cp_async4(rowbase + (unsigned int)(j << 7), src);
        }
        asm volatile("cp.async.commit_group;" ::: "memory");
        asm volatile("cp.async.wait_group 0;" ::: "memory");

        // Consume phase: lane reads its own 4 B (no cross-lane dependency).
        #pragma unroll 8
        for (int j = 0; j < m; j++) {
            float vj = __int_as_float(s_edges[wslot][j].y);
            unsigned int w = s_rows[wslot][j][lane];
            float2 xf = __half22float2(*(__half2*)&w);
            acc.x = fmaf(vj, xf.x, acc.x);
            acc.y = fmaf(vj, xf.y, acc.y);
        }
        __syncwarp();   // protect s_edges before next chunk overwrites
    }

    float2* o = (float2*)(out + (size_t)node * DIM);
    if (MODE == 0) {
        const float2* e = (node < NUM_USERS)
            ? (const float2*)user_emb + (size_t)node * (DIM / 2)
            : (const float2*)item_emb + (size_t)(node - NUM_USERS) * (DIM / 2);
        float2 ev = e[lane];
        o[lane] = make_float2(ev.x + acc.x, ev.y + acc.y);
        nxt[(size_t)node * (DIM / 2) + lane] = __floats2half2_rn(acc.x, acc.y);
    } else if (MODE == 1) {
        float2 a = o[lane];
        a.x += acc.x; a.y += acc.y;
        o[lane] = a;
        nxt[(size_t)node * (DIM / 2) + lane] = __floats2half2_rn(acc.x, acc.y);
    } else {
        float2 a = o[lane];
        a.x = (a.x + acc.x) * 0.25f;
        a.y = (a.y + acc.y) * 0.25f;
        o[lane] = a;
    }
}

// -------------------------------------------------------------------------
// Launch: 7 kernels, graph-capturable, no sync, no alloc.
// -------------------------------------------------------------------------
extern "C" void kernel_launch(void* const* d_in, const int* in_sizes, int n_in,
                              void* d_out, int out_size)
{
    const float* user_emb  = (const float*)d_in[0];
    const float* item_emb  = (const float*)d_in[1];
    const float* edge_vals = (const float*)d_in[2];
    const int*   edge_row  = (const int*)d_in[3];
    const int*   edge_col  = (const int*)d_in[4];
    float* out = (float*)d_out;

    __half2 *bufA, *bufB;
    cudaGetSymbolAddress((void**)&bufA, g_bufA);
    cudaGetSymbolAddress((void**)&bufB, g_bufB);

    const int conv_grid = (N_NODES * DIM / 8 + 255) / 256;
    const int e8_grid   = (NUM_EDGES / 8 + 255) / 256;
    const int gather_grid = (N_NODES + 7) / 8;   // 8 warps/block

    // Build fp16 input + CSR (re-done every replay: deterministic).
    lgcn_convert<<<conv_grid, 256>>>(user_emb, item_emb);
    lgcn_hist<<<e8_grid, 256>>>(edge_row);
    lgcn_scan<<<1, 1024>>>();
    lgcn_scatter<<<e8_grid, 256>>>(edge_vals, edge_row, edge_col);

    // 3 propagation layers, accumulation fused.
    lgcn_gather<0><<<gather_grid, 256>>>(bufA, user_emb, item_emb, bufB, out);
    lgcn_gather<1><<<gather_grid, 256>>>(bufB, user_emb, item_emb, bufA, out);
    lgcn_gather<2><<<gather_grid, 256>>>(bufA, user_emb, item_emb, nullptr, out);
}

// round 9
// speedup vs baseline: 1.2070x; 1.2070x over previous
#include <cuda_runtime.h>
#include <cuda_fp16.h>

#define NUM_USERS 100000
#define NUM_ITEMS 50000
#define N_NODES   150000
#define DIM       64
#define NUM_EDGES 4000000

// Scratch (allocation-free rule: __device__ globals).
__device__ __half2 g_bufA[N_NODES * DIM / 2];
__device__ __half2 g_bufB[N_NODES * DIM / 2];
__device__ int2    g_edges[NUM_EDGES];      // interleaved {col, val-bits}
__device__ int     g_hist[N_NODES];
__device__ int     g_rowptr[N_NODES + 1];
__device__ int     g_cursor[N_NODES];

// -------------------------------------------------------------------------
// Kernel 1: convert concat(user,item) embeddings -> fp16 bufA; zero hist.
// -------------------------------------------------------------------------
__global__ void lgcn_convert(const float* __restrict__ user_emb,
                             const float* __restrict__ item_emb)
{
    int i = blockIdx.x * blockDim.x + threadIdx.x;
    const int total8 = N_NODES * DIM / 8;
    if (i < total8) {
        const int user8 = NUM_USERS * DIM / 8;
        const float4* s = (i < user8)
            ? (const float4*)user_emb + 2 * (size_t)i
            : (const float4*)item_emb + 2 * (size_t)(i - user8);
        float4 a = s[0];
        float4 b = s[1];
        __half2 h0 = __floats2half2_rn(a.x, a.y);
        __half2 h1 = __floats2half2_rn(a.z, a.w);
        __half2 h2 = __floats2half2_rn(b.x, b.y);
        __half2 h3 = __floats2half2_rn(b.z, b.w);
        uint4 p;
        p.x = *(unsigned int*)&h0;
        p.y = *(unsigned int*)&h1;
        p.z = *(unsigned int*)&h2;
        p.w = *(unsigned int*)&h3;
        ((uint4*)g_bufA)[i] = p;
    }
    if (i < N_NODES) g_hist[i] = 0;
}

// -------------------------------------------------------------------------
// Kernel 2: degree histogram, 8 edges/thread (2x int4 loads).
// -------------------------------------------------------------------------
__global__ void lgcn_hist(const int* __restrict__ edge_row)
{
    int i = blockIdx.x * blockDim.x + threadIdx.x;
    if (i >= NUM_EDGES / 8) return;
    int4 r0 = ((const int4*)edge_row)[i * 2];
    int4 r1 = ((const int4*)edge_row)[i * 2 + 1];
    atomicAdd(&g_hist[r0.x], 1);
    atomicAdd(&g_hist[r0.y], 1);
    atomicAdd(&g_hist[r0.z], 1);
    atomicAdd(&g_hist[r0.w], 1);
    atomicAdd(&g_hist[r1.x], 1);
    atomicAdd(&g_hist[r1.y], 1);
    atomicAdd(&g_hist[r1.z], 1);
    atomicAdd(&g_hist[r1.w], 1);
}

// -------------------------------------------------------------------------
// Kernel 3: single-block exclusive scan -> row_ptr + cursor.
// -------------------------------------------------------------------------
__global__ void lgcn_scan()
{
    const int T = 1024;
    const int CHUNK = (N_NODES + T - 1) / T;   // 147
    __shared__ int s_part[T];

    int t   = threadIdx.x;
    int beg = t * CHUNK;
    int end = min(beg + CHUNK, N_NODES);

    int sum = 0;
    for (int i = beg; i < end; i++) sum += g_hist[i];
    s_part[t] = sum;
    __syncthreads();

    for (int off = 1; off < T; off <<= 1) {
        int v = (t >= off) ? s_part[t - off] : 0;
        __syncthreads();
        s_part[t] += v;
        __syncthreads();
    }

    int run = s_part[t] - sum;
    for (int i = beg; i < end; i++) {
        g_rowptr[i] = run;
        g_cursor[i] = run;
        run += g_hist[i];
    }
    if (t == 0) g_rowptr[N_NODES] = NUM_EDGES;
}

// -------------------------------------------------------------------------
// Kernel 4: scatter edges into row-sorted interleaved array, 8 edges/thread.
// -------------------------------------------------------------------------
__global__ void lgcn_scatter(const float* __restrict__ edge_vals,
                             const int*   __restrict__ edge_row,
                             const int*   __restrict__ edge_col)
{
    int i = blockIdx.x * blockDim.x + threadIdx.x;
    if (i >= NUM_EDGES / 8) return;
    int4   r0 = ((const int4*)edge_row)[i * 2];
    int4   r1 = ((const int4*)edge_row)[i * 2 + 1];
    int4   c0 = ((const int4*)edge_col)[i * 2];
    int4   c1 = ((const int4*)edge_col)[i * 2 + 1];
    float4 v0 = ((const float4*)edge_vals)[i * 2];
    float4 v1 = ((const float4*)edge_vals)[i * 2 + 1];

    int p0 = atomicAdd(&g_cursor[r0.x], 1);
    int p1 = atomicAdd(&g_cursor[r0.y], 1);
    int p2 = atomicAdd(&g_cursor[r0.z], 1);
    int p3 = atomicAdd(&g_cursor[r0.w], 1);
    int p4 = atomicAdd(&g_cursor[r1.x], 1);
    int p5 = atomicAdd(&g_cursor[r1.y], 1);
    int p6 = atomicAdd(&g_cursor[r1.z], 1);
    int p7 = atomicAdd(&g_cursor[r1.w], 1);

    g_edges[p0] = make_int2(c0.x, __float_as_int(v0.x));
    g_edges[p1] = make_int2(c0.y, __float_as_int(v0.y));
    g_edges[p2] = make_int2(c0.z, __float_as_int(v0.z));
    g_edges[p3] = make_int2(c0.w, __float_as_int(v0.w));
    g_edges[p4] = make_int2(c1.x, __float_as_int(v1.x));
    g_edges[p5] = make_int2(c1.y, __float_as_int(v1.y));
    g_edges[p6] = make_int2(c1.z, __float_as_int(v1.z));
    g_edges[p7] = make_int2(c1.w, __float_as_int(v1.w));
}

// -------------------------------------------------------------------------
// Kernel 5: warp-per-node CSR gather, fp16 rows, TWO edges per iteration.
// Half-warp h handles edge j+h: 16 lanes x uint2 (8 B) = full 128 B row in
// one LDG.64 shared by both edges.  Sentinel {0,0} edges make the inner
// loop branchless (reads row 0, accumulates 0).  fp32 accumulation,
// shfl_xor(16) fold at epilogue.
// MODE 0: out = emb_f32 + acc; nxt = half(acc).
// MODE 1: out += acc;          nxt = half(acc).
// MODE 2: out = (out + acc) * 0.25.
// -------------------------------------------------------------------------
template<int MODE>
__global__ void __launch_bounds__(256)
lgcn_gather(const __half2* __restrict__ cur,
            const float*   __restrict__ user_emb,
            const float*   __restrict__ item_emb,
            __half2*       __restrict__ nxt,
            float*         __restrict__ out)
{
    __shared__ int2 s_edges[8][32];
    const int wslot = threadIdx.x >> 5;
    const int lane  = threadIdx.x & 31;
    const int half  = lane >> 4;       // which edge of the pair
    const int dlane = lane & 15;       // 4-dim group within the row
    const int node  = blockIdx.x * 8 + wslot;
    if (node >= N_NODES) return;

    const int start = g_rowptr[node];
    const int end   = g_rowptr[node + 1];

    float4 acc = make_float4(0.f, 0.f, 0.f, 0.f);
    const char* curb = (const char*)cur;

    for (int base = start; base < end; base += 32) {
        int idx = base + lane;
        s_edges[wslot][lane] = (idx < end) ? g_edges[idx] : make_int2(0, 0);
        __syncwarp();
        const int m = min(32, end - base);
        #pragma unroll 8
        for (int j = 0; j < m; j += 2) {
            int2  cv = s_edges[wslot][j + half];
            float vj = __int_as_float(cv.y);
            uint2 w  = *(const uint2*)(curb + ((size_t)cv.x << 7) + (dlane << 3));
            float2 f0 = __half22float2(*(__half2*)&w.x);
            float2 f1 = __half22float2(*(__half2*)&w.y);
            acc.x = fmaf(vj, f0.x, acc.x);
            acc.y = fmaf(vj, f0.y, acc.y);
            acc.z = fmaf(vj, f1.x, acc.z);
            acc.w = fmaf(vj, f1.y, acc.w);
        }
        __syncwarp();
    }

    // Fold the two half-warp accumulators.
    acc.x += __shfl_xor_sync(0xffffffffu, acc.x, 16);
    acc.y += __shfl_xor_sync(0xffffffffu, acc.y, 16);
    acc.z += __shfl_xor_sync(0xffffffffu, acc.z, 16);
    acc.w += __shfl_xor_sync(0xffffffffu, acc.w, 16);

    if (half == 0) {
        float4* o = (float4*)(out + (size_t)node * DIM);
        if (MODE == 0) {
            const float4* e = (node < NUM_USERS)
                ? (const float4*)user_emb + (size_t)node * (DIM / 4)
                : (const float4*)item_emb + (size_t)(node - NUM_USERS) * (DIM / 4);
            float4 ev = e[dlane];
            o[dlane] = make_float4(ev.x + acc.x, ev.y + acc.y,
                                   ev.z + acc.z, ev.w + acc.w);
        } else if (MODE == 1) {
            float4 a = o[dlane];
            a.x += acc.x; a.y += acc.y; a.z += acc.z; a.w += acc.w;
            o[dlane] = a;
        } else {
            float4 a = o[dlane];
            a.x = (a.x + acc.x) * 0.25f;
            a.y = (a.y + acc.y) * 0.25f;
            a.z = (a.z + acc.z) * 0.25f;
            a.w = (a.w + acc.w) * 0.25f;
            o[dlane] = a;
        }
        if (MODE < 2) {
            __half2 h0 = __floats2half2_rn(acc.x, acc.y);
            __half2 h1 = __floats2half2_rn(acc.z, acc.w);
            uint2 p;
            p.x = *(unsigned int*)&h0;
            p.y = *(unsigned int*)&h1;
            ((uint2*)(nxt + (size_t)node * (DIM / 2)))[dlane] = p;
        }
    }
}

// -------------------------------------------------------------------------
// Launch: 7 kernels, graph-capturable, no sync, no alloc.
// -------------------------------------------------------------------------
extern "C" void kernel_launch(void* const* d_in, const int* in_sizes, int n_in,
                              void* d_out, int out_size)
{
    const float* user_emb  = (const float*)d_in[0];
    const float* item_emb  = (const float*)d_in[1];
    const float* edge_vals = (const float*)d_in[2];
    const int*   edge_row  = (const int*)d_in[3];
    const int*   edge_col  = (const int*)d_in[4];
    float* out = (float*)d_out;

    __half2 *bufA, *bufB;
    cudaGetSymbolAddress((void**)&bufA, g_bufA);
    cudaGetSymbolAddress((void**)&bufB, g_bufB);

    const int conv_grid = (N_NODES * DIM / 8 + 255) / 256;
    const int e8_grid   = (NUM_EDGES / 8 + 255) / 256;
    const int gather_grid = (N_NODES + 7) / 8;   // 8 warps/block

    // Build fp16 input + CSR (re-done every replay: deterministic).
    lgcn_convert<<<conv_grid, 256>>>(user_emb, item_emb);
    lgcn_hist<<<e8_grid, 256>>>(edge_row);
    lgcn_scan<<<1, 1024>>>();
    lgcn_scatter<<<e8_grid, 256>>>(edge_vals, edge_row, edge_col);

    // 3 propagation layers, accumulation fused.
    lgcn_gather<0><<<gather_grid, 256>>>(bufA, user_emb, item_emb, bufB, out);
    lgcn_gather<1><<<gather_grid, 256>>>(bufB, user_emb, item_emb, bufA, out);
    lgcn_gather<2><<<gather_grid, 256>>>(bufA, user_emb, item_emb, nullptr, out);
}

// round 10
// speedup vs baseline: 1.2731x; 1.0547x over previous
#include <cuda_runtime.h>
#include <cuda_fp16.h>

#define NUM_USERS 100000
#define NUM_ITEMS 50000
#define N_NODES   150000
#define DIM       64
#define NUM_EDGES 4000000

// Scratch (allocation-free rule: __device__ globals).
__device__ __half2 g_bufA[N_NODES * DIM / 2];
__device__ __half2 g_bufB[N_NODES * DIM / 2];
__device__ int2    g_edges[NUM_EDGES];      // interleaved {col, val-bits}
__device__ int     g_hist[N_NODES];
__device__ int     g_rowptr[N_NODES + 1];
__device__ int     g_cursor[N_NODES];

// -------------------------------------------------------------------------
// Kernel 1: convert concat(user,item) embeddings -> fp16 bufA; zero hist.
// -------------------------------------------------------------------------
__global__ void lgcn_convert(const float* __restrict__ user_emb,
                             const float* __restrict__ item_emb)
{
    int i = blockIdx.x * blockDim.x + threadIdx.x;
    const int total8 = N_NODES * DIM / 8;
    if (i < total8) {
        const int user8 = NUM_USERS * DIM / 8;
        const float4* s = (i < user8)
            ? (const float4*)user_emb + 2 * (size_t)i
            : (const float4*)item_emb + 2 * (size_t)(i - user8);
        float4 a = s[0];
        float4 b = s[1];
        __half2 h0 = __floats2half2_rn(a.x, a.y);
        __half2 h1 = __floats2half2_rn(a.z, a.w);
        __half2 h2 = __floats2half2_rn(b.x, b.y);
        __half2 h3 = __floats2half2_rn(b.z, b.w);
        uint4 p;
        p.x = *(unsigned int*)&h0;
        p.y = *(unsigned int*)&h1;
        p.z = *(unsigned int*)&h2;
        p.w = *(unsigned int*)&h3;
        ((uint4*)g_bufA)[i] = p;
    }
    if (i < N_NODES) g_hist[i] = 0;
}

// -------------------------------------------------------------------------
// Kernel 2: degree histogram, 8 edges/thread; streaming (evict-first) reads.
// -------------------------------------------------------------------------
__global__ void lgcn_hist(const int* __restrict__ edge_row)
{
    int i = blockIdx.x * blockDim.x + threadIdx.x;
    if (i >= NUM_EDGES / 8) return;
    int4 r0 = __ldcs((const int4*)edge_row + i * 2);
    int4 r1 = __ldcs((const int4*)edge_row + i * 2 + 1);
    atomicAdd(&g_hist[r0.x], 1);
    atomicAdd(&g_hist[r0.y], 1);
    atomicAdd(&g_hist[r0.z], 1);
    atomicAdd(&g_hist[r0.w], 1);
    atomicAdd(&g_hist[r1.x], 1);
    atomicAdd(&g_hist[r1.y], 1);
    atomicAdd(&g_hist[r1.z], 1);
    atomicAdd(&g_hist[r1.w], 1);
}

// -------------------------------------------------------------------------
// Kernel 3: single-block exclusive scan -> row_ptr + cursor.
// -------------------------------------------------------------------------
__global__ void lgcn_scan()
{
    const int T = 1024;
    const int CHUNK = (N_NODES + T - 1) / T;   // 147
    __shared__ int s_part[T];

    int t   = threadIdx.x;
    int beg = t * CHUNK;
    int end = min(beg + CHUNK, N_NODES);

    int sum = 0;
    for (int i = beg; i < end; i++) sum += g_hist[i];
    s_part[t] = sum;
    __syncthreads();

    for (int off = 1; off < T; off <<= 1) {
        int v = (t >= off) ? s_part[t - off] : 0;
        __syncthreads();
        s_part[t] += v;
        __syncthreads();
    }

    int run = s_part[t] - sum;
    for (int i = beg; i < end; i++) {
        g_rowptr[i] = run;
        g_cursor[i] = run;
        run += g_hist[i];
    }
    if (t == 0) g_rowptr[N_NODES] = NUM_EDGES;
}

// -------------------------------------------------------------------------
// Kernel 4: scatter edges into row-sorted interleaved array, 8 edges/thread.
// Streaming reads AND streaming writes (g_edges is a write-once stream).
// -------------------------------------------------------------------------
__global__ void lgcn_scatter(const float* __restrict__ edge_vals,
                             const int*   __restrict__ edge_row,
                             const int*   __restrict__ edge_col)
{
    int i = blockIdx.x * blockDim.x + threadIdx.x;
    if (i >= NUM_EDGES / 8) return;
    int4   r0 = __ldcs((const int4*)edge_row + i * 2);
    int4   r1 = __ldcs((const int4*)edge_row + i * 2 + 1);
    int4   c0 = __ldcs((const int4*)edge_col + i * 2);
    int4   c1 = __ldcs((const int4*)edge_col + i * 2 + 1);
    float4 v0 = __ldcs((const float4*)edge_vals + i * 2);
    float4 v1 = __ldcs((const float4*)edge_vals + i * 2 + 1);

    int p0 = atomicAdd(&g_cursor[r0.x], 1);
    int p1 = atomicAdd(&g_cursor[r0.y], 1);
    int p2 = atomicAdd(&g_cursor[r0.z], 1);
    int p3 = atomicAdd(&g_cursor[r0.w], 1);
    int p4 = atomicAdd(&g_cursor[r1.x], 1);
    int p5 = atomicAdd(&g_cursor[r1.y], 1);
    int p6 = atomicAdd(&g_cursor[r1.z], 1);
    int p7 = atomicAdd(&g_cursor[r1.w], 1);

    __stcs(&g_edges[p0], make_int2(c0.x, __float_as_int(v0.x)));
    __stcs(&g_edges[p1], make_int2(c0.y, __float_as_int(v0.y)));
    __stcs(&g_edges[p2], make_int2(c0.z, __float_as_int(v0.z)));
    __stcs(&g_edges[p3], make_int2(c0.w, __float_as_int(v0.w)));
    __stcs(&g_edges[p4], make_int2(c1.x, __float_as_int(v1.x)));
    __stcs(&g_edges[p5], make_int2(c1.y, __float_as_int(v1.y)));
    __stcs(&g_edges[p6], make_int2(c1.z, __float_as_int(v1.z)));
    __stcs(&g_edges[p7], make_int2(c1.w, __float_as_int(v1.w)));
}

// -------------------------------------------------------------------------
// Kernel 5: warp-per-node CSR gather (R7-proven shape), fp16 rows.
// g_edges read with evict-first so the 32 MB stream never evicts the
// resident cur/nxt/out working set from L2.
// MODE 0: out = emb_f32 + acc; nxt = half(acc).
// MODE 1: out += acc;          nxt = half(acc).
// MODE 2: out = (out + acc) * 0.25.
// -------------------------------------------------------------------------
template<int MODE>
__global__ void __launch_bounds__(256)
lgcn_gather(const __half2* __restrict__ cur,
            const float*   __restrict__ user_emb,
            const float*   __restrict__ item_emb,
            __half2*       __restrict__ nxt,
            float*         __restrict__ out)
{
    __shared__ int2 s_edges[8][32];
    const int wslot = threadIdx.x >> 5;
    const int lane  = threadIdx.x & 31;
    const int node  = blockIdx.x * 8 + wslot;
    if (node >= N_NODES) return;

    const int start = g_rowptr[node];
    const int end   = g_rowptr[node + 1];

    float2 acc = make_float2(0.f, 0.f);

    for (int base = start; base < end; base += 32) {
        int idx = base + lane;
        if (idx < end) s_edges[wslot][lane] = __ldcs(&g_edges[idx]);
        __syncwarp();
        const int n = min(32, end - base);
        #pragma unroll 8
        for (int j = 0; j < n; j++) {
            int2  cv = s_edges[wslot][j];
            float vj = __int_as_float(cv.y);
            __half2 x = cur[(size_t)cv.x * (DIM / 2) + lane];
            float2 xf = __half22float2(x);
            acc.x += vj * xf.x;
            acc.y += vj * xf.y;
        }
        __syncwarp();
    }

    float2* o = (float2*)(out + (size_t)node * DIM);
    if (MODE == 0) {
        const float2* e = (node < NUM_USERS)
            ? (const float2*)user_emb + (size_t)node * (DIM / 2)
            : (const float2*)item_emb + (size_t)(node - NUM_USERS) * (DIM / 2);
        float2 ev = e[lane];
        o[lane] = make_float2(ev.x + acc.x, ev.y + acc.y);
        nxt[(size_t)node * (DIM / 2) + lane] = __floats2half2_rn(acc.x, acc.y);
    } else if (MODE == 1) {
        float2 a = o[lane];
        a.x += acc.x; a.y += acc.y;
        o[lane] = a;
        nxt[(size_t)node * (DIM / 2) + lane] = __floats2half2_rn(acc.x, acc.y);
    } else {
        float2 a = o[lane];
        a.x = (a.x + acc.x) * 0.25f;
        a.y = (a.y + acc.y) * 0.25f;
        o[lane] = a;
    }
}

// -------------------------------------------------------------------------
// Launch: 7 kernels, graph-capturable, no sync, no alloc.
// -------------------------------------------------------------------------
extern "C" void kernel_launch(void* const* d_in, const int* in_sizes, int n_in,
                              void* d_out, int out_size)
{
    const float* user_emb  = (const float*)d_in[0];
    const float* item_emb  = (const float*)d_in[1];
    const float* edge_vals = (const float*)d_in[2];
    const int*   edge_row  = (const int*)d_in[3];
    const int*   edge_col  = (const int*)d_in[4];
    float* out = (float*)d_out;

    __half2 *bufA, *bufB;
    cudaGetSymbolAddress((void**)&bufA, g_bufA);
    cudaGetSymbolAddress((void**)&bufB, g_bufB);

    const int conv_grid = (N_NODES * DIM / 8 + 255) / 256;
    const int e8_grid   = (NUM_EDGES / 8 + 255) / 256;
    const int gather_grid = (N_NODES + 7) / 8;   // 8 warps/block

    // Build fp16 input + CSR (re-done every replay: deterministic).
    lgcn_convert<<<conv_grid, 256>>>(user_emb, item_emb);
    lgcn_hist<<<e8_grid, 256>>>(edge_row);
    lgcn_scan<<<1, 1024>>>();
    lgcn_scatter<<<e8_grid, 256>>>(edge_vals, edge_row, edge_col);

    // 3 propagation layers, accumulation fused.
    lgcn_gather<0><<<gather_grid, 256>>>(bufA, user_emb, item_emb, bufB, out);
    lgcn_gather<1><<<gather_grid, 256>>>(bufB, user_emb, item_emb, bufA, out);
    lgcn_gather<2><<<gather_grid, 256>>>(bufA, user_emb, item_emb, nullptr, out);
}